// round 4
// baseline (speedup 1.0000x reference)
#include <cuda_runtime.h>
#include <cstdint>

// Problem dims
constexpr int BATCH = 64;
constexpr int SEQ   = 512;
constexpr int EMB   = 256;
constexpr int HID   = 512;
constexpr int OUTD  = 1000;
constexpr int KD    = HID + EMB;   // 768

// Persistent-kernel config
constexpr int NCTA     = 128;           // 1 CTA per SM, all resident -> spin barrier safe
constexpr int UNITS    = HID / NCTA;    // 4 hidden units per CTA
constexpr int NCOLS    = 4 * UNITS;     // 16 gate columns (f,i,c,o x units)
constexpr int NTHREADS = 256;
constexpr int NTEAMS   = 4;
constexpr int CHUNK_K  = 64;            // team t owns k-chunks {64t, 256+64t (h), 512+64t (emb)}
constexpr int CPAD     = CHUNK_K + 4;   // 68: float4-aligned, 4-bank row skew (conflict-free LDS.128)
constexpr int WPAD     = KD + 4;        // 772: float4-aligned, 4-bank col skew (conflict-free LDS.128)
constexpr int TEAM_BUF = BATCH * CPAD;  // 4352 floats per staging buffer
constexpr int GPITCH   = NCOLS + 1;     // 17: odd pitch -> conflict-free reduce STS

typedef unsigned long long u64;

// Device scratch (static — no runtime allocs allowed)
__device__ float g_emb[SEQ * BATCH * EMB];     // [s][b][e]
__device__ float g_hbuf[2][BATCH * HID];       // double-buffered hidden state
__device__ unsigned int g_bar;                 // grid barrier counter

__device__ __forceinline__ void fma2(u64 &d, u64 a, u64 b) {
    asm("fma.rn.f32x2 %0, %1, %2, %0;" : "+l"(d) : "l"(a), "l"(b));
}
__device__ __forceinline__ float pairsum(u64 v) {
    float lo, hi;
    asm("mov.b64 {%0,%1}, %2;" : "=f"(lo), "=f"(hi) : "l"(v));
    return lo + hi;
}
__device__ __forceinline__ float sigf(float x) { return 1.0f / (1.0f + expf(-x)); }

__device__ __forceinline__ void cp16(float* smem_dst, const float* gsrc) {
    uint32_t sa = (uint32_t)__cvta_generic_to_shared(smem_dst);
    asm volatile("cp.async.cg.shared.global [%0], [%1], 16;" :: "r"(sa), "l"(gsrc));
}
__device__ __forceinline__ void cp_commit()  { asm volatile("cp.async.commit_group;" ::: "memory"); }
__device__ __forceinline__ void cp_wait0()   { asm volatile("cp.async.wait_group 0;" ::: "memory"); }
__device__ __forceinline__ void cp_wait1()   { asm volatile("cp.async.wait_group 1;" ::: "memory"); }

// ---------------------------------------------------------------------------
// Embedding gather: g_emb[s][b][:] = embed_w[x[b][s]][:]  (+ barrier reset)
// ---------------------------------------------------------------------------
__global__ void embed_kernel(const int* __restrict__ x, const float* __restrict__ ew) {
    if (blockIdx.x == 0 && threadIdx.x == 0) g_bar = 0u;
    int i  = blockIdx.x * blockDim.x + threadIdx.x;   // SEQ*BATCH*EMB/4 threads
    int e4 = i & 63;                                   // EMB/4 = 64
    int b  = (i >> 6) & 63;
    int s  = i >> 12;
    int tok = x[b * SEQ + s];
    float4 v = reinterpret_cast<const float4*>(ew + (long)tok * EMB)[e4];
    reinterpret_cast<float4*>(g_emb + ((long)s * BATCH + b) * EMB)[e4] = v;
}

// ---------------------------------------------------------------------------
// Persistent LSTM kernel. CTA ci owns hidden units [4ci, 4ci+4).
// Per-step schedule (per team, buffers bufE/bufH swap by step parity):
//   [bufE holds emb_s, prefetched last step]
//   compute emb PART1            <- absorbs inter-CTA barrier skew
//   grid-barrier WAIT
//   cp.async hA -> bufH
//   compute emb PART2            <- hides hA L2 latency
//   wait hA; cp.async hB -> bufE
//   compute hA                   <- hides hB L2 latency
//   cp.async emb_{s+1} -> bufH
//   wait hB; compute hB
//   reduce -> activations -> write h -> barrier ARRIVE
// Cell state c lives in registers of the owning (b,unit) thread.
// ---------------------------------------------------------------------------
__global__ void __launch_bounds__(NTHREADS, 1)
lstm_kernel(const float* __restrict__ h0, const float* __restrict__ c0,
            const float* __restrict__ Wf, const float* __restrict__ bf,
            const float* __restrict__ Wi, const float* __restrict__ bi,
            const float* __restrict__ Wc, const float* __restrict__ bc,
            const float* __restrict__ Wo, const float* __restrict__ bo,
            float* __restrict__ out_hidden)
{
    extern __shared__ float smem[];
    float* s_w    = smem;                                   // 16*772          = 12352
    float* s_comb = s_w + NCOLS * WPAD;                     // 4 teams*2*4352  = 34816
    float* s_g    = s_comb + NTEAMS * 2 * TEAM_BUF;         // 4*64*17         = 4352
    float* s_b    = s_g + NTEAMS * BATCH * GPITCH;          // 16
    // total 51536 floats = 206144 bytes

    const int tid = threadIdx.x;
    const int j0  = blockIdx.x * UNITS;

    // --- one-time: weights + biases into SMEM ---
    for (int idx = tid; idx < NCOLS * KD; idx += NTHREADS) {
        int col = idx / KD;
        int k   = idx - col * KD;
        int u   = col & 3;
        const float* W = (col < 4) ? Wf : (col < 8) ? Wi : (col < 12) ? Wc : Wo;
        s_w[col * WPAD + k] = W[k * HID + j0 + u];
    }
    if (tid < NCOLS) {
        int u = tid & 3;
        const float* Bp = (tid < 4) ? bf : (tid < 8) ? bi : (tid < 12) ? bc : bo;
        s_b[tid] = Bp[j0 + u];
    }

    // --- activation role: thread owns (b=ab, unit=au) ---
    const int ab = tid >> 2;
    const int au = tid & 3;
    float c_reg = c0[ab * HID + j0 + au];

    // --- compute role: team over K, 4b x 4c register tile ---
    const int team  = tid >> 6;         // 0..3
    const int tt    = tid & 63;
    const int tx    = tt & 3;           // cols {tx, tx+4, tx+8, tx+12}
    const int ty    = tt >> 2;          // batches {ty, ty+16, ty+32, ty+48}
    float* buf0 = s_comb + team * 2 * TEAM_BUF;
    float* buf1 = buf0 + TEAM_BUF;

    // stage one [64 x 64] chunk via cp.async (16 x 16B per thread, team-cooperative)
    auto stage_async = [&](float* dst, const float* src, int stride, int k0) {
        #pragma unroll 4
        for (int n = 0; n < 16; ++n) {
            int i   = tt + 64 * n;
            int row = i >> 4;                  // / (CHUNK_K/4 = 16)
            int q   = i & 15;
            cp16(dst + row * CPAD + (q << 2), src + row * stride + k0 + (q << 2));
        }
    };

    u64 acc[4][4];
    auto compute = [&](const float* cbuf, int kg0, int kbeg, int kend) {
        #pragma unroll 4
        for (int kk = kbeg; kk < kend; kk += 4) {
            ulonglong2 w0 = *reinterpret_cast<const ulonglong2*>(s_w + (tx     ) * WPAD + kg0 + kk);
            ulonglong2 w1 = *reinterpret_cast<const ulonglong2*>(s_w + (tx +  4) * WPAD + kg0 + kk);
            ulonglong2 w2 = *reinterpret_cast<const ulonglong2*>(s_w + (tx +  8) * WPAD + kg0 + kk);
            ulonglong2 w3 = *reinterpret_cast<const ulonglong2*>(s_w + (tx + 12) * WPAD + kg0 + kk);
            #pragma unroll
            for (int r = 0; r < 4; ++r) {
                ulonglong2 cb = *reinterpret_cast<const ulonglong2*>(cbuf + (r * 16 + ty) * CPAD + kk);
                fma2(acc[r][0], cb.x, w0.x); fma2(acc[r][0], cb.y, w0.y);
                fma2(acc[r][1], cb.x, w1.x); fma2(acc[r][1], cb.y, w1.y);
                fma2(acc[r][2], cb.x, w2.x); fma2(acc[r][2], cb.y, w2.y);
                fma2(acc[r][3], cb.x, w3.x); fma2(acc[r][3], cb.y, w3.y);
            }
        }
    };

    __syncthreads();   // weights visible

    // prefetch emb chunk for s=0 into buf0
    stage_async(buf0, g_emb, EMB, CHUNK_K * team);
    cp_commit();       // pending: {emb_0}

    for (int s = 0; s < SEQ; ++s) {
        const float* hc   = (s == 0) ? h0 : g_hbuf[s & 1];
        const int    e    = s & 1;
        float* bufE = e ? buf1 : buf0;   // holds emb_s (prefetched)
        float* bufH = e ? buf0 : buf1;   // stale (emb_{s-1}), free to overwrite

        #pragma unroll
        for (int r = 0; r < 4; ++r)
            #pragma unroll
            for (int j = 0; j < 4; ++j) acc[r][j] = 0ULL;

        const int kgE = HID + CHUNK_K * team;   // emb weight offset
        const int kgA = CHUNK_K * team;         // hA weight offset
        const int kgB = 256 + CHUNK_K * team;   // hB weight offset

        // ---- emb PART1 (barrier-independent; absorbs skew) ----
        cp_wait0();                      // emb_s staged (pending -> {})
        __syncthreads();
        compute(bufE, kgE, 0, CHUNK_K / 2);

        // ---- grid-barrier WAIT (arrive happened at end of previous step) ----
        if (tid == 0 && s > 0) {
            unsigned target = (unsigned)s * NCTA;
            while (*((volatile unsigned int*)&g_bar) < target) { }
            __threadfence();
        }
        __syncthreads();

        // ---- issue hA; emb PART2 hides its latency ----
        stage_async(bufH, hc, HID, kgA);     // pending: {hA}
        cp_commit();
        compute(bufE, kgE, CHUNK_K / 2, CHUNK_K);

        cp_wait0();                      // hA ready (pending -> {})
        __syncthreads();                 // all threads done reading bufE (emb complete)

        // ---- issue hB into bufE; hA compute hides its latency ----
        stage_async(bufE, hc, HID, kgB);     // pending: {hB}
        cp_commit();
        compute(bufH, kgA, 0, CHUNK_K);

        __syncthreads();                 // all threads done reading bufH

        // ---- prefetch next emb into bufH (becomes bufE next step) ----
        {
            int sn = (s + 1 < SEQ) ? s + 1 : s;
            stage_async(bufH, g_emb + (long)sn * (BATCH * EMB), EMB, CHUNK_K * team);
            cp_commit();                 // pending: {hB, embN}
        }

        cp_wait1();                      // hB ready (pending -> {embN})
        __syncthreads();
        compute(bufE, kgB, 0, CHUNK_K);

        // ---- per-team partial sums -> SMEM slabs (pitch 17: conflict-free) ----
        #pragma unroll
        for (int r = 0; r < 4; ++r) {
            int brow = r * 16 + ty;
            #pragma unroll
            for (int j = 0; j < 4; ++j)
                s_g[team * (BATCH * GPITCH) + brow * GPITCH + (tx + 4 * j)] = pairsum(acc[r][j]);
        }
        __syncthreads();

        // ---- activation + state update by owning (b,u) thread ----
        {
            const int base = ab * GPITCH;
            const int T = BATCH * GPITCH;
            float pre_f = s_b[au]
                        + s_g[base + au] + s_g[T + base + au] + s_g[2*T + base + au] + s_g[3*T + base + au];
            float pre_i = s_b[4 + au]
                        + s_g[base+4+au] + s_g[T + base+4+au] + s_g[2*T + base+4+au] + s_g[3*T + base+4+au];
            float pre_c = s_b[8 + au]
                        + s_g[base+8+au] + s_g[T + base+8+au] + s_g[2*T + base+8+au] + s_g[3*T + base+8+au];
            float pre_o = s_b[12 + au]
                        + s_g[base+12+au] + s_g[T + base+12+au] + s_g[2*T + base+12+au] + s_g[3*T + base+12+au];
            float fg = sigf(pre_f);
            float ig = sigf(pre_i);
            float cg = tanhf(pre_c);
            float og = sigf(pre_o);
            c_reg = fg * c_reg + ig * cg;
            float hval = og * tanhf(c_reg);
            g_hbuf[(s + 1) & 1][ab * HID + j0 + au] = hval;
            if (s == SEQ - 1) out_hidden[ab * HID + j0 + au] = hval;
        }
        __syncthreads();   // h writes done block-wide before arrival

        // ---- grid-barrier ARRIVE (early; wait deferred into next step) ----
        if (tid == 0 && s < SEQ - 1) {
            __threadfence();
            atomicAdd(&g_bar, 1u);
        }
    }

    cp_wait0();   // drain the final (unused) emb prefetch before exit
}

// ---------------------------------------------------------------------------
// Final dense: out[b][o] = h_final[b] . W_d[:,o] + b_d[o]
// SEQ even -> final h is in g_hbuf[0].
// ---------------------------------------------------------------------------
__global__ void dense_kernel(const float* __restrict__ Wd, const float* __restrict__ bd,
                             float* __restrict__ out)
{
    int o = blockIdx.x * 128 + threadIdx.x;
    int b = blockIdx.y;
    if (o >= OUTD) return;
    const float* h = g_hbuf[0] + b * HID;
    float acc = bd[o];
    #pragma unroll 8
    for (int k = 0; k < HID; ++k)
        acc += h[k] * Wd[k * OUTD + o];
    out[b * OUTD + o] = acc;
}

// ---------------------------------------------------------------------------
extern "C" void kernel_launch(void* const* d_in, const int* in_sizes, int n_in,
                              void* d_out, int out_size)
{
    const int*   x      = (const int*)  d_in[0];
    const float* hidden = (const float*)d_in[1];
    const float* c      = (const float*)d_in[2];
    const float* ew     = (const float*)d_in[3];
    const float* Wf     = (const float*)d_in[4];
    const float* bf     = (const float*)d_in[5];
    const float* Wi     = (const float*)d_in[6];
    const float* bi     = (const float*)d_in[7];
    const float* Wc     = (const float*)d_in[8];
    const float* bc     = (const float*)d_in[9];
    const float* Wo     = (const float*)d_in[10];
    const float* bo     = (const float*)d_in[11];
    const float* Wd     = (const float*)d_in[12];
    const float* bd     = (const float*)d_in[13];
    float* out = (float*)d_out;   // [B*OUTD output][B*HID hidden]

    // 1) embedding gather (+ barrier counter reset)
    embed_kernel<<<(SEQ * BATCH * EMB / 4) / 256, 256>>>(x, ew);

    // 2) persistent recurrent kernel
    const size_t smem_bytes =
        (size_t)(NCOLS * WPAD + NTEAMS * 2 * TEAM_BUF + NTEAMS * BATCH * GPITCH + NCOLS) * sizeof(float);
    cudaFuncSetAttribute(lstm_kernel, cudaFuncAttributeMaxDynamicSharedMemorySize, (int)smem_bytes);
    lstm_kernel<<<NCTA, NTHREADS, smem_bytes>>>(hidden, c, Wf, bf, Wi, bi, Wc, bc, Wo, bo,
                                                out + BATCH * OUTD);

    // 3) output projection
    dense_kernel<<<dim3((OUTD + 127) / 128, BATCH), 128>>>(Wd, bd, out);
}

// round 5
// speedup vs baseline: 1.0311x; 1.0311x over previous
#include <cuda_runtime.h>
#include <cstdint>

// Problem dims
constexpr int BATCH = 64;
constexpr int SEQ   = 512;
constexpr int EMB   = 256;
constexpr int HID   = 512;
constexpr int OUTD  = 1000;
constexpr int KD    = HID + EMB;   // 768

// Persistent-kernel config
constexpr int NCTA     = 128;           // 1 CTA per SM, all resident -> spin barrier safe
constexpr int UNITS    = HID / NCTA;    // 4 hidden units per CTA
constexpr int NCOLS    = 4 * UNITS;     // 16 gate columns (f,i,c,o x units)
constexpr int NTHREADS = 512;           // 16 warps = 4 per SMSP (latency hiding)
constexpr int NTEAMS   = 4;             // 128-thread teams
constexpr int TEAM_T   = 128;
constexpr int CHUNK_K  = 64;            // team t owns k-chunks {64t, 256+64t (h), 512+64t (emb)}
constexpr int CPAD     = CHUNK_K + 4;   // 68: float4-aligned, 4-bank row skew (conflict-free LDS.128)
constexpr int WPAD     = KD + 4;        // 772: float4-aligned, 4-bank col skew (conflict-free LDS.128)
constexpr int TEAM_BUF = BATCH * CPAD;  // 4352 floats per staging buffer
constexpr int GPITCH   = NCOLS + 1;     // 17: odd pitch reduces reduce-STS conflicts

typedef unsigned long long u64;

// Device scratch (static — no runtime allocs allowed)
__device__ float g_emb[SEQ * BATCH * EMB];     // [s][b][e]
__device__ float g_hbuf[2][BATCH * HID];       // double-buffered hidden state
__device__ unsigned int g_bar;                 // grid barrier counter

__device__ __forceinline__ void fma2(u64 &d, u64 a, u64 b) {
    asm("fma.rn.f32x2 %0, %1, %2, %0;" : "+l"(d) : "l"(a), "l"(b));
}
__device__ __forceinline__ float pairsum(u64 v) {
    float lo, hi;
    asm("mov.b64 {%0,%1}, %2;" : "=f"(lo), "=f"(hi) : "l"(v));
    return lo + hi;
}
__device__ __forceinline__ float sigf(float x) { return 1.0f / (1.0f + expf(-x)); }

__device__ __forceinline__ void cp16(float* smem_dst, const float* gsrc) {
    uint32_t sa = (uint32_t)__cvta_generic_to_shared(smem_dst);
    asm volatile("cp.async.cg.shared.global [%0], [%1], 16;" :: "r"(sa), "l"(gsrc));
}
__device__ __forceinline__ void cp_commit()  { asm volatile("cp.async.commit_group;" ::: "memory"); }
__device__ __forceinline__ void cp_wait0()   { asm volatile("cp.async.wait_group 0;" ::: "memory"); }
__device__ __forceinline__ void cp_wait1()   { asm volatile("cp.async.wait_group 1;" ::: "memory"); }

// Named barrier scoped to one 128-thread team (ids 1..4; 0 is __syncthreads)
__device__ __forceinline__ void team_bar(int id) {
    asm volatile("bar.sync %0, %1;" :: "r"(id), "n"(TEAM_T) : "memory");
}

// ---------------------------------------------------------------------------
// Embedding gather: g_emb[s][b][:] = embed_w[x[b][s]][:]  (+ barrier reset)
// ---------------------------------------------------------------------------
__global__ void embed_kernel(const int* __restrict__ x, const float* __restrict__ ew) {
    if (blockIdx.x == 0 && threadIdx.x == 0) g_bar = 0u;
    int i  = blockIdx.x * blockDim.x + threadIdx.x;   // SEQ*BATCH*EMB/4 threads
    int e4 = i & 63;                                   // EMB/4 = 64
    int b  = (i >> 6) & 63;
    int s  = i >> 12;
    int tok = x[b * SEQ + s];
    float4 v = reinterpret_cast<const float4*>(ew + (long)tok * EMB)[e4];
    reinterpret_cast<float4*>(g_emb + ((long)s * BATCH + b) * EMB)[e4] = v;
}

// ---------------------------------------------------------------------------
// Persistent LSTM kernel. CTA ci owns hidden units [4ci, 4ci+4).
// 512 threads: 4 teams x 128. Team tile: 64b x 16cols over its 64-K chunk,
// thread tile 4b x 2c (acc[4][2], f32x2-packed). Per-team named barriers
// decouple teams; block syncs only at barrier-release / reduce / arrive.
// Per-step schedule (bufE/bufH swap by parity):
//   cp_wait(emb_s) -> teambar -> emb PART1
//   [grid-barrier spin by tid0] __syncthreads
//   issue hA->bufH ; emb PART2 ; teambar ; issue hB->bufE
//   wait(hA) ; teambar ; compute hA ; teambar ; issue emb_{s+1}->bufH
//   wait(hB) ; teambar ; compute hB
//   reduce -> __syncthreads -> activations -> __syncthreads -> arrive
// Cell state c lives in registers of the owning (b,unit) thread (tid<256).
// ---------------------------------------------------------------------------
__global__ void __launch_bounds__(NTHREADS, 1)
lstm_kernel(const float* __restrict__ h0, const float* __restrict__ c0,
            const float* __restrict__ Wf, const float* __restrict__ bf,
            const float* __restrict__ Wi, const float* __restrict__ bi,
            const float* __restrict__ Wc, const float* __restrict__ bc,
            const float* __restrict__ Wo, const float* __restrict__ bo,
            float* __restrict__ out_hidden)
{
    extern __shared__ float smem[];
    float* s_w    = smem;                                   // 16*772          = 12352
    float* s_comb = s_w + NCOLS * WPAD;                     // 4 teams*2*4352  = 34816
    float* s_g    = s_comb + NTEAMS * 2 * TEAM_BUF;         // 4*64*17         = 4352
    float* s_b    = s_g + NTEAMS * BATCH * GPITCH;          // 16
    // total 51536 floats = 206144 bytes

    const int tid = threadIdx.x;
    const int j0  = blockIdx.x * UNITS;

    // --- one-time: weights + biases into SMEM ---
    for (int idx = tid; idx < NCOLS * KD; idx += NTHREADS) {
        int col = idx / KD;
        int k   = idx - col * KD;
        int u   = col & 3;
        const float* W = (col < 4) ? Wf : (col < 8) ? Wi : (col < 12) ? Wc : Wo;
        s_w[col * WPAD + k] = W[k * HID + j0 + u];
    }
    if (tid < NCOLS) {
        int u = tid & 3;
        const float* Bp = (tid < 4) ? bf : (tid < 8) ? bi : (tid < 12) ? bc : bo;
        s_b[tid] = Bp[j0 + u];
    }

    // --- activation role (tid < 256): thread owns (b=ab, unit=au) ---
    const int ab = tid >> 2;
    const int au = tid & 3;
    float c_reg = 0.0f;
    if (tid < 256) c_reg = c0[ab * HID + j0 + au];

    // --- compute role: team over K, 4b x 2c register tile ---
    const int team  = tid >> 7;         // 0..3
    const int tt    = tid & 127;
    const int tx    = tt & 7;           // cols {tx, tx+8}
    const int ty    = tt >> 3;          // 0..15 ; batches {ty, ty+16, ty+32, ty+48}
    const int bid   = 1 + team;         // named barrier id
    float* buf0 = s_comb + team * 2 * TEAM_BUF;
    float* buf1 = buf0 + TEAM_BUF;

    // stage one [64 x 64] chunk via cp.async (8 x 16B per thread, team-cooperative)
    auto stage_async = [&](float* dst, const float* src, int stride, int k0) {
        #pragma unroll
        for (int n = 0; n < 8; ++n) {
            int i   = tt + TEAM_T * n;
            int row = i >> 4;                  // / (CHUNK_K/4 = 16)
            int q   = i & 15;
            cp16(dst + row * CPAD + (q << 2), src + row * stride + k0 + (q << 2));
        }
    };

    u64 acc[4][2];
    auto compute = [&](const float* cbuf, int kg0, int kbeg, int kend) {
        #pragma unroll 4
        for (int kk = kbeg; kk < kend; kk += 4) {
            ulonglong2 w0 = *reinterpret_cast<const ulonglong2*>(s_w + (tx    ) * WPAD + kg0 + kk);
            ulonglong2 w1 = *reinterpret_cast<const ulonglong2*>(s_w + (tx + 8) * WPAD + kg0 + kk);
            #pragma unroll
            for (int r = 0; r < 4; ++r) {
                ulonglong2 cb = *reinterpret_cast<const ulonglong2*>(cbuf + (r * 16 + ty) * CPAD + kk);
                fma2(acc[r][0], cb.x, w0.x); fma2(acc[r][0], cb.y, w0.y);
                fma2(acc[r][1], cb.x, w1.x); fma2(acc[r][1], cb.y, w1.y);
            }
        }
    };

    __syncthreads();   // weights visible

    // prefetch emb chunk for s=0 into buf0
    stage_async(buf0, g_emb, EMB, CHUNK_K * team);
    cp_commit();       // pending: {emb_0}

    for (int s = 0; s < SEQ; ++s) {
        const float* hc   = (s == 0) ? h0 : g_hbuf[s & 1];
        const int    e    = s & 1;
        float* bufE = e ? buf1 : buf0;   // holds emb_s (prefetched)
        float* bufH = e ? buf0 : buf1;   // stale, free to overwrite

        #pragma unroll
        for (int r = 0; r < 4; ++r) {
            acc[r][0] = 0ULL; acc[r][1] = 0ULL;
        }

        const int kgE = HID + CHUNK_K * team;   // emb weight offset
        const int kgA = CHUNK_K * team;         // hA weight offset
        const int kgB = 256 + CHUNK_K * team;   // hB weight offset

        // ---- emb PART1 (barrier-independent; absorbs skew) ----
        cp_wait0();                      // own emb_s cps landed
        team_bar(bid);                   // whole team's cps landed
        compute(bufE, kgE, 0, CHUNK_K / 2);

        // ---- grid-barrier WAIT folded into a block sync ----
        if (tid == 0 && s > 0) {
            unsigned target = (unsigned)s * NCTA;
            while (*((volatile unsigned int*)&g_bar) < target) { }
            // no reader-side fence needed: h is read via cp.async.cg (L2-direct),
            // and the writer's __threadfence ordered h-stores before the counter.
        }
        __syncthreads();

        // ---- issue hA; emb PART2 hides its latency ----
        stage_async(bufH, hc, HID, kgA);     // pending: {hA}
        cp_commit();
        compute(bufE, kgE, CHUNK_K / 2, CHUNK_K);
        team_bar(bid);                   // team done reading bufE

        // ---- issue hB into bufE; hA compute hides its latency ----
        stage_async(bufE, hc, HID, kgB);     // pending: {hA, hB}
        cp_commit();

        cp_wait1();                      // own hA landed (pending -> {hB})
        team_bar(bid);                   // whole team's hA landed
        compute(bufH, kgA, 0, CHUNK_K);
        team_bar(bid);                   // team done reading bufH

        // ---- prefetch next emb into bufH (becomes bufE next step) ----
        {
            int sn = (s + 1 < SEQ) ? s + 1 : s;
            stage_async(bufH, g_emb + (long)sn * (BATCH * EMB), EMB, CHUNK_K * team);
            cp_commit();                 // pending: {hB, embN}
        }

        cp_wait1();                      // own hB landed (pending -> {embN})
        team_bar(bid);                   // whole team's hB landed
        compute(bufE, kgB, 0, CHUNK_K);

        // ---- per-team partial sums -> SMEM slabs ----
        #pragma unroll
        for (int r = 0; r < 4; ++r) {
            int brow = r * 16 + ty;
            s_g[team * (BATCH * GPITCH) + brow * GPITCH + tx    ] = pairsum(acc[r][0]);
            s_g[team * (BATCH * GPITCH) + brow * GPITCH + tx + 8] = pairsum(acc[r][1]);
        }
        __syncthreads();

        // ---- activation + state update by owning (b,u) thread ----
        if (tid < 256) {
            const int base = ab * GPITCH;
            const int T = BATCH * GPITCH;
            float pre_f = s_b[au]
                        + s_g[base + au] + s_g[T + base + au] + s_g[2*T + base + au] + s_g[3*T + base + au];
            float pre_i = s_b[4 + au]
                        + s_g[base+4+au] + s_g[T + base+4+au] + s_g[2*T + base+4+au] + s_g[3*T + base+4+au];
            float pre_c = s_b[8 + au]
                        + s_g[base+8+au] + s_g[T + base+8+au] + s_g[2*T + base+8+au] + s_g[3*T + base+8+au];
            float pre_o = s_b[12 + au]
                        + s_g[base+12+au] + s_g[T + base+12+au] + s_g[2*T + base+12+au] + s_g[3*T + base+12+au];
            float fg = sigf(pre_f);
            float ig = sigf(pre_i);
            float cg = tanhf(pre_c);
            float og = sigf(pre_o);
            c_reg = fg * c_reg + ig * cg;
            float hval = og * tanhf(c_reg);
            g_hbuf[(s + 1) & 1][ab * HID + j0 + au] = hval;
            if (s == SEQ - 1) out_hidden[ab * HID + j0 + au] = hval;
        }
        __syncthreads();   // h writes done block-wide before arrival

        // ---- grid-barrier ARRIVE (early; wait deferred into next step) ----
        if (tid == 0 && s < SEQ - 1) {
            __threadfence();             // release: h stores visible before count
            atomicAdd(&g_bar, 1u);
        }
    }

    cp_wait0();   // drain the final (unused) emb prefetch before exit
}

// ---------------------------------------------------------------------------
// Final dense: out[b][o] = h_final[b] . W_d[:,o] + b_d[o]
// SEQ even -> final h is in g_hbuf[0].
// ---------------------------------------------------------------------------
__global__ void dense_kernel(const float* __restrict__ Wd, const float* __restrict__ bd,
                             float* __restrict__ out)
{
    int o = blockIdx.x * 128 + threadIdx.x;
    int b = blockIdx.y;
    if (o >= OUTD) return;
    const float* h = g_hbuf[0] + b * HID;
    float acc = bd[o];
    #pragma unroll 8
    for (int k = 0; k < HID; ++k)
        acc += h[k] * Wd[k * OUTD + o];
    out[b * OUTD + o] = acc;
}

// ---------------------------------------------------------------------------
extern "C" void kernel_launch(void* const* d_in, const int* in_sizes, int n_in,
                              void* d_out, int out_size)
{
    const int*   x      = (const int*)  d_in[0];
    const float* hidden = (const float*)d_in[1];
    const float* c      = (const float*)d_in[2];
    const float* ew     = (const float*)d_in[3];
    const float* Wf     = (const float*)d_in[4];
    const float* bf     = (const float*)d_in[5];
    const float* Wi     = (const float*)d_in[6];
    const float* bi     = (const float*)d_in[7];
    const float* Wc     = (const float*)d_in[8];
    const float* bc     = (const float*)d_in[9];
    const float* Wo     = (const float*)d_in[10];
    const float* bo     = (const float*)d_in[11];
    const float* Wd     = (const float*)d_in[12];
    const float* bd     = (const float*)d_in[13];
    float* out = (float*)d_out;   // [B*OUTD output][B*HID hidden]

    // 1) embedding gather (+ barrier counter reset)
    embed_kernel<<<(SEQ * BATCH * EMB / 4) / 256, 256>>>(x, ew);

    // 2) persistent recurrent kernel
    const size_t smem_bytes =
        (size_t)(NCOLS * WPAD + NTEAMS * 2 * TEAM_BUF + NTEAMS * BATCH * GPITCH + NCOLS) * sizeof(float);
    cudaFuncSetAttribute(lstm_kernel, cudaFuncAttributeMaxDynamicSharedMemorySize, (int)smem_bytes);
    lstm_kernel<<<NCTA, NTHREADS, smem_bytes>>>(hidden, c, Wf, bf, Wi, bi, Wc, bc, Wo, bo,
                                                out + BATCH * OUTD);

    // 3) output projection
    dense_kernel<<<dim3((OUTD + 127) / 128, BATCH), 128>>>(Wd, bd, out);
}